// round 4
// baseline (speedup 1.0000x reference)
#include <cuda_runtime.h>
#include <math.h>
#include <stdint.h>

#define BB     512
#define NN     4096
#define DD     128
#define HH     8
#define TPREV  2048
#define NW     4        // warps per CTA
#define NT     128      // threads per CTA
#define HALF1  (TPREV/2)   // 1024 attn1 keys per rank
#define HALF2  (NN/2)      // 2048 attn2 keys per rank

__device__ __forceinline__ unsigned smem_u32(const void* p) {
    unsigned a;
    asm("{ .reg .u64 t; cvta.to.shared.u64 t, %1; cvt.u32.u64 %0, t; }" : "=r"(a) : "l"(p));
    return a;
}
__device__ __forceinline__ unsigned mapa_peer(unsigned addr, unsigned rank) {
    unsigned r;
    asm("mapa.shared::cluster.u32 %0, %1, %2;" : "=r"(r) : "r"(addr), "r"(rank));
    return r;
}
__device__ __forceinline__ float ld_dsmem(unsigned addr) {
    float v;
    asm volatile("ld.shared::cluster.f32 %0, [%1];" : "=f"(v) : "r"(addr));
    return v;
}
#define CLUSTER_SYNC() do { \
    asm volatile("barrier.cluster.arrive.aligned;" ::: "memory"); \
    asm volatile("barrier.cluster.wait.aligned;"   ::: "memory"); \
} while (0)

__device__ __forceinline__ float warpReduceSum(float v) {
#pragma unroll
    for (int o = 16; o > 0; o >>= 1) v += __shfl_xor_sync(0xffffffffu, v, o);
    return v;
}

// out[j] = sum_i x[i]*W[j*128+i] + bias[j].  128 threads, 4 warps x 32 rows.
__device__ __noinline__ void gemv128(const float* __restrict__ W, const float* __restrict__ bias,
                                     const float* __restrict__ x, float* __restrict__ out, int tid)
{
    int warp = tid >> 5, lane = tid & 31;
    float4 xv = ((const float4*)x)[lane];
#pragma unroll 4
    for (int jj = 0; jj < 32; jj++) {
        int j = warp * 32 + jj;
        float4 wv = ((const float4*)(W + j * DD))[lane];
        float p = wv.x * xv.x + wv.y * xv.y + wv.z * xv.z + wv.w * xv.w;
        p = warpReduceSum(p);
        if (lane == 0) out[j] = p + bias[j];
    }
}

__device__ __noinline__ void layernorm128(float* __restrict__ x, const float* __restrict__ g,
                                          const float* __restrict__ bb, int tid)
{
    if (tid < 32) {
        float v0 = x[tid], v1 = x[tid + 32], v2 = x[tid + 64], v3 = x[tid + 96];
        float s = warpReduceSum(v0 + v1 + v2 + v3);
        float mu = s * (1.0f / 128.0f);
        float d0 = v0 - mu, d1 = v1 - mu, d2 = v2 - mu, d3 = v3 - mu;
        float sq = warpReduceSum(d0 * d0 + d1 * d1 + d2 * d2 + d3 * d3);
        float rstd = rsqrtf(sq * (1.0f / 128.0f) + 1e-5f);
        x[tid]      = d0 * rstd * g[tid]      + bb[tid];
        x[tid + 32] = d1 * rstd * g[tid + 32] + bb[tid + 32];
        x[tid + 64] = d2 * rstd * g[tid + 64] + bb[tid + 64];
        x[tid + 96] = d3 * rstd * g[tid + 96] + bb[tid + 96];
    }
}

__device__ __forceinline__ void online_update(const float4& kk, const float4& vv,
                                              const float4& q4, float& m, float& l, float4& o)
{
    float s = kk.x * q4.x + kk.y * q4.y + kk.z * q4.z + kk.w * q4.w;
    s += __shfl_xor_sync(0xffffffffu, s, 1);
    s += __shfl_xor_sync(0xffffffffu, s, 2);
    s *= 0.25f;                               // 1/sqrt(dh=16)
    float mn = fmaxf(m, s);
    float sc = __expf(m - mn);
    float p  = __expf(s - mn);
    l = l * sc + p;
    o.x = o.x * sc + p * vv.x;
    o.y = o.y * sc + p * vv.y;
    o.z = o.z * sc + p * vv.z;
    o.w = o.w * sc + p * vv.w;
    m = mn;
}

// CTA-local warp merge -> per-head (M,L, unnormalized O) into exchange buffer,
// then DSMEM exchange with peer rank, final normalized att into out.
// red: NW*128 + NW*8 + NW*8 floats. xm[8], xl[8], xo[128] per-attention exchange bufs.
__device__ void reduce_exchange(float m, float l, float4 o,
                                float* __restrict__ red,
                                float* __restrict__ xm, float* __restrict__ xl,
                                float* __restrict__ xo,
                                float* __restrict__ out, unsigned peer, int tid)
{
    const int lane = tid & 31, warp = tid >> 5;
    float* red_o = red;
    float* red_m = red + NW * 128;
    float* red_l = red_m + NW * 8;

    ((float4*)(red_o + warp * 128))[lane] = o;
    if ((lane & 3) == 0) {
        red_m[warp * 8 + (lane >> 2)] = m;
        red_l[warp * 8 + (lane >> 2)] = l;
    }
    __syncthreads();

    int hh = tid >> 4;
    float M = -INFINITY;
#pragma unroll
    for (int w = 0; w < NW; w++) M = fmaxf(M, red_m[w * 8 + hh]);
    float L = 0.f, O = 0.f;
#pragma unroll
    for (int w = 0; w < NW; w++) {
        float sc = __expf(red_m[w * 8 + hh] - M);
        L += red_l[w * 8 + hh] * sc;
        O += red_o[w * 128 + tid] * sc;
    }
    xo[tid] = O;
    if ((tid & 15) == 0) { xm[hh] = M; xl[hh] = L; }

    CLUSTER_SYNC();

    // read peer's partial via DSMEM
    float Mp = ld_dsmem(mapa_peer(smem_u32(xm + hh), peer));
    float Lp = ld_dsmem(mapa_peer(smem_u32(xl + hh), peer));
    float Op = ld_dsmem(mapa_peer(smem_u32(xo + tid), peer));

    float Mc = fmaxf(M, Mp);
    float scl = __expf(M - Mc), scp = __expf(Mp - Mc);
    out[tid] = (O * scl + Op * scp) / (L * scl + Lp * scp);
    __syncthreads();
}

// Attention 1 half: unmasked stream over HALF1 keys; rank 0 also folds in the
// appended current-step k/v (from smem) via warp 0.
__device__ void attn1_core(const float4* __restrict__ Kb, const float4* __restrict__ Vb,
                           const float* __restrict__ q,
                           const float* __restrict__ kex, const float* __restrict__ vex,
                           bool do_extra, float& m, float& l, float4& o, int tid)
{
    const int lane = tid & 31, warp = tid >> 5;
    float4 q4 = ((const float4*)q)[lane];
    m = -INFINITY; l = 0.0f; o = make_float4(0.f, 0.f, 0.f, 0.f);

    for (int t0 = warp; t0 < HALF1; t0 += NW * 4) {
        float4 kk[4], vv[4];
#pragma unroll
        for (int u = 0; u < 4; u++) {
            int t = t0 + u * NW;
            kk[u] = Kb[(size_t)t * 32 + lane];
            vv[u] = Vb[(size_t)t * 32 + lane];
        }
#pragma unroll
        for (int u = 0; u < 4; u++) online_update(kk[u], vv[u], q4, m, l, o);
    }
    if (do_extra && warp == 0) {
        float4 kk = ((const float4*)kex)[lane];
        float4 vv = ((const float4*)vex)[lane];
        online_update(kk, vv, q4, m, l, o);
    }
}

// Attention 2 half: HALF2 keys with mask-skip. Warp w owns contiguous [w*512,(w+1)*512).
__device__ void attn2_core(const float4* __restrict__ Kb, const float4* __restrict__ Vb,
                           const unsigned* __restrict__ mbits,
                           const float* __restrict__ q,
                           float& m, float& l, float4& o, int tid)
{
    const int lane = tid & 31, warp = tid >> 5;
    float4 q4 = ((const float4*)q)[lane];
    m = -INFINITY; l = 0.0f; o = make_float4(0.f, 0.f, 0.f, 0.f);

    const int per_warp = HALF2 / NW;   // 512
    const int start = warp * per_warp;

    for (int base = start; base < start + per_warp; base += 32) {
        unsigned word = mbits[base >> 5];
        if (word == 0xffffffffu) continue;
#pragma unroll
        for (int j0 = 0; j0 < 32; j0 += 4) {
            float4 kk[4], vv[4];
            bool act[4];
#pragma unroll
            for (int u = 0; u < 4; u++) {
                act[u] = ((word >> (j0 + u)) & 1u) == 0u;
                if (act[u]) {
                    int t = base + j0 + u;
                    kk[u] = Kb[(size_t)t * 32 + lane];
                    vv[u] = Vb[(size_t)t * 32 + lane];
                }
            }
#pragma unroll
            for (int u = 0; u < 4; u++)
                if (act[u]) online_update(kk[u], vv[u], q4, m, l, o);
        }
    }
}

__global__ void __launch_bounds__(NT, 8) __cluster_dims__(2, 1, 1)
ARD_67765993997201_kernel(const float* __restrict__ ht_in,
                          const float* __restrict__ key,
                          const float* __restrict__ value,
                          const int*   __restrict__ mask,
                          const float* __restrict__ kprev,
                          const float* __restrict__ vprev,
                          const float* __restrict__ W,
                          const float* __restrict__ bvec,
                          const float* __restrict__ ln_g,
                          const float* __restrict__ ln_b,
                          float* __restrict__ out)
{
    const int tid = threadIdx.x;
    const int lane = tid & 31, warp = tid >> 5;
    unsigned rank;
    asm("mov.u32 %0, %%cluster_ctarank;" : "=r"(rank));
    const unsigned peer = rank ^ 1u;
    const int b = blockIdx.x >> 1;

    __shared__ float ht[128], qb[128], kb[128], vb[128], tmp[128], att[128];
    __shared__ float red[NW * 128 + NW * 8 * 2];
    __shared__ float x1m[8], x1l[8], x1o[128];
    __shared__ float x2m[8], x2l[8], x2o[128];
    __shared__ unsigned mbits[HALF2 / 32];         // 64 words

    if (tid < 128) ht[tid] = ht_in[(size_t)b * DD + tid];

    // Build mask bitset for own half early (DRAM latency hides under what follows).
    {
        const int* mb = mask + (size_t)b * NN + (size_t)rank * HALF2;
#pragma unroll
        for (int r = 0; r < (HALF2 / 32) / NW; r++) {   // 16 rounds
            int widx = r * NW + warp;
            unsigned bal = __ballot_sync(0xffffffffu, mb[widx * 32 + lane] == 1);
            if (lane == 0) mbits[widx] = bal;
        }
    }
    __syncthreads();

    // q, k, v projections (redundant in both ranks)
    gemv128(W + 0 * DD * DD, bvec + 0 * DD, ht, qb, tid);
    gemv128(W + 1 * DD * DD, bvec + 1 * DD, ht, kb, tid);
    gemv128(W + 2 * DD * DD, bvec + 2 * DD, ht, vb, tid);
    __syncthreads();

    // Attention 1 over own half of [kprev; k],[vprev; v]
    {
        float m, l; float4 o;
        attn1_core((const float4*)kprev + ((size_t)b * TPREV + rank * HALF1) * 32,
                   (const float4*)vprev + ((size_t)b * TPREV + rank * HALF1) * 32,
                   qb, kb, vb, rank == 0, m, l, o, tid);
        reduce_exchange(m, l, o, red, x1m, x1l, x1o, att, peer, tid);
    }

    gemv128(W + 3 * DD * DD, bvec + 3 * DD, att, tmp, tid);
    __syncthreads();
    ht[tid] += tmp[tid];
    __syncthreads();
    layernorm128(ht, ln_g + 0 * DD, ln_b + 0 * DD, tid);
    __syncthreads();

    gemv128(W + 4 * DD * DD, bvec + 4 * DD, ht, qb, tid);
    __syncthreads();

    // Attention 2 over own half of key/value with mask-skip
    {
        float m, l; float4 o;
        attn2_core((const float4*)key   + ((size_t)b * NN + rank * HALF2) * 32,
                   (const float4*)value + ((size_t)b * NN + rank * HALF2) * 32,
                   mbits, qb, m, l, o, tid);
        reduce_exchange(m, l, o, red, x2m, x2l, x2o, att, peer, tid);
    }

    gemv128(W + 5 * DD * DD, bvec + 5 * DD, att, tmp, tid);
    __syncthreads();
    ht[tid] += tmp[tid];
    __syncthreads();
    layernorm128(ht, ln_g + 1 * DD, ln_b + 1 * DD, tid);
    __syncthreads();

    // FFN
    gemv128(W + 7 * DD * DD, bvec + 7 * DD, ht, tmp, tid);
    __syncthreads();
    tmp[tid] = fmaxf(tmp[tid], 0.0f);
    __syncthreads();
    gemv128(W + 6 * DD * DD, bvec + 6 * DD, tmp, qb, tid);
    __syncthreads();
    ht[tid] += qb[tid];
    __syncthreads();
    layernorm128(ht, ln_g + 2 * DD, ln_b + 2 * DD, tid);
    __syncthreads();

    out[(size_t)b * DD + tid] = ht[tid];

    // Keep SMEM alive until peer's DSMEM reads of x2* are done.
    CLUSTER_SYNC();
}

extern "C" void kernel_launch(void* const* d_in, const int* in_sizes, int n_in,
                              void* d_out, int out_size)
{
    const float* ht    = (const float*)d_in[0];
    const float* key   = (const float*)d_in[1];
    const float* value = (const float*)d_in[2];
    const int*   mask  = (const int*)  d_in[3];
    const float* kprev = (const float*)d_in[4];
    const float* vprev = (const float*)d_in[5];
    const float* W     = (const float*)d_in[6];
    const float* bvec  = (const float*)d_in[7];
    const float* ln_g  = (const float*)d_in[8];
    const float* ln_b  = (const float*)d_in[9];
    float* out = (float*)d_out;

    ARD_67765993997201_kernel<<<BB * 2, NT>>>(ht, key, value, mask, kprev, vprev,
                                              W, bvec, ln_g, ln_b, out);
}